// round 13
// baseline (speedup 1.0000x reference)
#include <cuda_runtime.h>
#include <math.h>

#define T_TOK 1024
#define E_EXP 16
#define K_TOP 4
#define H_DIM 2048
#define I_DIM 2048
#define CAP   512
#define N1    (2*I_DIM)   /* 4096 */

// ---------------- scratch (device globals; no runtime allocation) ----------------
__device__ int   g_w1p[E_EXP*(H_DIM/4)*N1];     // [E][K/4][2I] int32: byte j = k = 4*k4+j
__device__ int   g_w2p[E_EXP*(I_DIM/4)*H_DIM];  // [E][K/4][H]
__device__ int   g_xq[T_TOK*(H_DIM/4)];         // packed int8 tokens [T][512]
__device__ float g_xs[T_TOK];
__device__ int   g_topk_i[T_TOK*K_TOP];
__device__ float g_topk_w[T_TOK*K_TOP];
__device__ int   g_rowsrc[E_EXP*CAP];
__device__ int   g_slot[T_TOK*K_TOP];
__device__ int   g_cnt[E_EXP];
__device__ float g_act[(size_t)E_EXP*CAP*I_DIM];   // swiglu output
__device__ int   g_hq[E_EXP*CAP*(I_DIM/4)];        // requantized act
__device__ float g_hs[E_EXP*CAP];
__device__ float g_z[(size_t)E_EXP*CAP*H_DIM];     // GEMM2 output

// ---------------- helpers ----------------
__device__ __forceinline__ int packb(float a, float b, float c, float d) {
    return ( __float2int_rn(a) & 0xff)
         | ((__float2int_rn(b) & 0xff) << 8)
         | ((__float2int_rn(c) & 0xff) << 16)
         | ((__float2int_rn(d) & 0xff) << 24);
}
__device__ __forceinline__ int q8c(float v, float s) {
    int q = __float2int_rn(v / s);
    q = max(-127, min(127, q));
    return q & 0xff;
}
// IMMA m16n8k32 s8*s8+s32
__device__ __forceinline__ void mma_s8(int* c, const int* a, const int* b) {
    asm volatile("mma.sync.aligned.m16n8k32.row.col.s32.s8.s8.s32 "
        "{%0,%1,%2,%3}, {%4,%5,%6,%7}, {%8,%9}, {%0,%1,%2,%3};"
        : "+r"(c[0]), "+r"(c[1]), "+r"(c[2]), "+r"(c[3])
        : "r"(a[0]), "r"(a[1]), "r"(a[2]), "r"(a[3]), "r"(b[0]), "r"(b[1]));
}

// ---------------- weight repack: f32 (int values) -> K-packed int8 ----------------
__global__ void k_pack(const float* __restrict__ in, int which, int Kd, int Nd) {
    int* __restrict__ out = which ? g_w2p : g_w1p;
    long long i4  = (long long)blockIdx.x * blockDim.x + threadIdx.x;
    long long lin = i4 * 4;
    long long perE = (long long)(Kd >> 2) * Nd;
    int e  = (int)(lin / perE);
    long long rem = lin - (long long)e * perE;
    int k4 = (int)(rem / Nd);
    int n  = (int)(rem - (long long)k4 * Nd);
    const float* p = in + ((long long)e * Kd + 4 * k4) * Nd + n;
    float4 r0 = *(const float4*)(p);
    float4 r1 = *(const float4*)(p + Nd);
    float4 r2 = *(const float4*)(p + 2 * Nd);
    float4 r3 = *(const float4*)(p + 3 * Nd);
    int4 o;
    o.x = packb(r0.x, r1.x, r2.x, r3.x);
    o.y = packb(r0.y, r1.y, r2.y, r3.y);
    o.z = packb(r0.z, r1.z, r2.z, r3.z);
    o.w = packb(r0.w, r1.w, r2.w, r3.w);
    *(int4*)(out + lin) = o;
}

// ---------------- gating: softmax + top-4 + renormalize ----------------
__global__ void k_gate(const float* __restrict__ logits) {
    int t = blockIdx.x, lane = threadIdx.x;
    float v = (lane < E_EXP) ? logits[t * E_EXP + lane] : -1e30f;
    float m = v;
    #pragma unroll
    for (int o = 16; o; o >>= 1) m = fmaxf(m, __shfl_xor_sync(0xffffffffu, m, o));
    float cur = (lane < E_EXP) ? expf(v - m) : -1.0f;
    float w[K_TOP]; int id[K_TOP];
    #pragma unroll
    for (int k = 0; k < K_TOP; k++) {
        float bv = cur; int bi = lane;
        #pragma unroll
        for (int o = 16; o; o >>= 1) {
            float ov = __shfl_xor_sync(0xffffffffu, bv, o);
            int   oi = __shfl_xor_sync(0xffffffffu, bi, o);
            if (ov > bv || (ov == bv && oi < bi)) { bv = ov; bi = oi; }
        }
        w[k] = bv; id[k] = bi;
        if (lane == bi) cur = -1.0f;
    }
    float s = w[0] + w[1] + w[2] + w[3];
    if (lane < K_TOP) {
        g_topk_i[t * K_TOP + lane] = id[lane];
        g_topk_w[t * K_TOP + lane] = w[lane] / s;
    }
}

// ---------------- per-row dynamic int8 quant ----------------
__global__ void k_quant(const float* __restrict__ xin, int which) {
    const float* x; int* q; float* s;
    if (which == 0) { x = xin;  q = g_xq; s = g_xs; }
    else            { x = g_act; q = g_hq; s = g_hs; }
    int r = blockIdx.x, t = threadIdx.x;
    const float* row = x + (long long)r * 2048;
    float4 a = *(const float4*)(row + t * 8);
    float4 b = *(const float4*)(row + t * 8 + 4);
    float mx = fmaxf(fmaxf(fmaxf(fabsf(a.x), fabsf(a.y)), fmaxf(fabsf(a.z), fabsf(a.w))),
                     fmaxf(fmaxf(fabsf(b.x), fabsf(b.y)), fmaxf(fabsf(b.z), fabsf(b.w))));
    __shared__ float sm[256];
    sm[t] = mx; __syncthreads();
    #pragma unroll
    for (int o = 128; o; o >>= 1) { if (t < o) sm[t] = fmaxf(sm[t], sm[t + o]); __syncthreads(); }
    float scale = fmaxf(sm[0] / 127.0f, 1e-8f);
    int2 o2;
    o2.x = q8c(a.x, scale) | (q8c(a.y, scale) << 8) | (q8c(a.z, scale) << 16) | (q8c(a.w, scale) << 24);
    o2.y = q8c(b.x, scale) | (q8c(b.y, scale) << 8) | (q8c(b.z, scale) << 16) | (q8c(b.w, scale) << 24);
    *(int2*)(q + (long long)r * 512 + t * 2) = o2;
    if (t == 0) s[r] = scale;
}

// ---------------- routing ----------------
__global__ void k_route() {
    int w = threadIdx.x >> 5, lane = threadIdx.x & 31;
    int base = 0;
    for (int c = 0; c < (T_TOK * K_TOP) / 32; c++) {
        int i = c * 32 + lane;
        int e = g_topk_i[i];
        unsigned mask = __ballot_sync(0xffffffffu, e == w);
        if (e == w) {
            int pos = base + __popc(mask & ((1u << lane) - 1u));
            if (pos < CAP) { g_rowsrc[w * CAP + pos] = i >> 2; g_slot[i] = w * CAP + pos; }
            else           { g_slot[i] = -1; }
        }
        base += __popc(mask);
    }
    int cnt = min(base, CAP);
    if (lane == 0) g_cnt[w] = cnt;
    for (int p = cnt + lane; p < CAP; p += 32) g_rowsrc[w * CAP + p] = -1;
}

// ---------------- GEMM1: IMMA m16n8k32, CTA 128m x (64 gate + 64 up), K=2048 ----------------
// grid (32, 4, 16). 8 warps = 4m x 2n; warp tile 32m x 32n (gate) + 32m x 32n (up).
__global__ void __launch_bounds__(256) k_gemm1(const float* __restrict__ w1s,
                                               const float* __restrict__ w1b,
                                               const float* __restrict__ smooth) {
    int e = blockIdx.z, mt = blockIdx.y, ng = blockIdx.x;
    int cnt = g_cnt[e];
    if (mt * 128 >= cnt) return;

    __shared__ int As[2][8 * 136];     // [k4][m], stride 136
    __shared__ int Bs[2][8 * 136];     // [k4][cc 0..127], stride 136 (cc<64 gate, >=64 up)
    __shared__ int s_src[128];
    __shared__ float s_xs[128];
    __shared__ float s_gs[64], s_gb[64], s_us[64], s_ub[64], s_sm[64];

    int t = threadIdx.x;
    if (t < 128) {
        int s = g_rowsrc[e * CAP + mt * 128 + t];
        s_src[t] = s;
        s_xs[t] = (s >= 0) ? g_xs[s] : 0.0f;
    }
    if (t < 64) {
        int n = ng * 64 + t;
        s_gs[t] = w1s[e * N1 + n];
        s_gb[t] = w1b[e * N1 + n];
        s_us[t] = w1s[e * N1 + I_DIM + n];
        s_ub[t] = w1b[e * N1 + I_DIM + n];
        s_sm[t] = smooth[e * I_DIM + n];
    }
    __syncthreads();

    int lane = t & 31, wid = t >> 5;
    int wm = (wid & 3) * 32;           // warp m offset
    int wn = (wid >> 2) * 32;          // warp n offset within 64 gate cols
    int grp = lane >> 2, qid = lane & 3;

    // staging indices
    int am = t >> 1, ajj = (t & 1) * 4;                    // A: 2 threads/row, int4 each
    int bj = t >> 5, bn4 = t & 31;                         // B: warp per k4 row
    int srcm = s_src[am];
    int bcc = bn4 * 4;
    long long bcol = (bcc < 64) ? (long long)(ng * 64 + bcc)
                                : (long long)(I_DIM + ng * 64 + (bcc - 64));
    const int* bptr = g_w1p + (long long)e * 512 * N1 + bcol;
    const int* aptr = (srcm >= 0) ? (g_xq + srcm * 512 + ajj) : (const int*)0;

    int accg[2][4][4], accu[2][4][4];
    #pragma unroll
    for (int i = 0; i < 2; i++)
        #pragma unroll
        for (int j = 0; j < 4; j++)
            #pragma unroll
            for (int k = 0; k < 4; k++) { accg[i][j][k] = 0; accu[i][j][k] = 0; }

    // prologue: stage chunk 0 into buf 0
    {
        int4 av = aptr ? *(const int4*)(aptr) : make_int4(0, 0, 0, 0);
        As[0][(ajj + 0) * 136 + am] = av.x;
        As[0][(ajj + 1) * 136 + am] = av.y;
        As[0][(ajj + 2) * 136 + am] = av.z;
        As[0][(ajj + 3) * 136 + am] = av.w;
        int4 bv = *(const int4*)(bptr + (long long)bj * N1);
        *(int4*)&Bs[0][bj * 136 + bn4 * 4] = bv;
    }
    __syncthreads();

    for (int kt = 0; kt < 64; kt++) {
        int buf = kt & 1;
        if (kt + 1 < 64) {
            int k4b = (kt + 1) * 8;
            int nb = buf ^ 1;
            int4 av = aptr ? *(const int4*)(aptr + k4b) : make_int4(0, 0, 0, 0);
            As[nb][(ajj + 0) * 136 + am] = av.x;
            As[nb][(ajj + 1) * 136 + am] = av.y;
            As[nb][(ajj + 2) * 136 + am] = av.z;
            As[nb][(ajj + 3) * 136 + am] = av.w;
            int4 bv = *(const int4*)(bptr + (long long)(k4b + bj) * N1);
            *(int4*)&Bs[nb][bj * 136 + bn4 * 4] = bv;
        }
        int a[2][4];
        #pragma unroll
        for (int mf = 0; mf < 2; mf++) {
            int mr = wm + mf * 16 + grp;
            a[mf][0] = As[buf][qid * 136 + mr];
            a[mf][1] = As[buf][qid * 136 + mr + 8];
            a[mf][2] = As[buf][(qid + 4) * 136 + mr];
            a[mf][3] = As[buf][(qid + 4) * 136 + mr + 8];
        }
        #pragma unroll
        for (int nf = 0; nf < 4; nf++) {
            int cc = wn + nf * 8 + grp;
            int bg[2] = { Bs[buf][qid * 136 + cc], Bs[buf][(qid + 4) * 136 + cc] };
            int bu[2] = { Bs[buf][qid * 136 + 64 + cc], Bs[buf][(qid + 4) * 136 + 64 + cc] };
            #pragma unroll
            for (int mf = 0; mf < 2; mf++) {
                mma_s8(accg[mf][nf], a[mf], bg);
                mma_s8(accu[mf][nf], a[mf], bu);
            }
        }
        __syncthreads();
    }

    // epilogue: dequant + swiglu, write g_act (cols ng*64 .. +64)
    #pragma unroll
    for (int mf = 0; mf < 2; mf++) {
        int r0 = wm + mf * 16 + grp;
        int r1 = r0 + 8;
        float xs0 = s_xs[r0], xs1 = s_xs[r1];
        float* d0 = g_act + ((size_t)e * CAP + mt * 128 + r0) * I_DIM + (size_t)ng * 64;
        float* d1 = g_act + ((size_t)e * CAP + mt * 128 + r1) * I_DIM + (size_t)ng * 64;
        #pragma unroll
        for (int nf = 0; nf < 4; nf++) {
            int nl = wn + nf * 8 + qid * 2;
            #pragma unroll
            for (int c = 0; c < 2; c++) {
                int n = nl + c;
                float gs = s_gs[n], gbv = s_gb[n], us = s_us[n], ubv = s_ub[n], smv = s_sm[n];
                // row r0: acc idx c, row r1: acc idx c+2
                float yg0 = (float)accg[mf][nf][c]     * xs0 * gs + gbv;
                float yu0 = (float)accu[mf][nf][c]     * xs0 * us + ubv;
                float yg1 = (float)accg[mf][nf][c + 2] * xs1 * gs + gbv;
                float yu1 = (float)accu[mf][nf][c + 2] * xs1 * us + ubv;
                float gg0 = fminf(yg0, 7.0f), uu0 = fminf(fmaxf(yu0, -7.0f), 7.0f);
                float gg1 = fminf(yg1, 7.0f), uu1 = fminf(fmaxf(yu1, -7.0f), 7.0f);
                d0[n] = gg0 / (1.0f + expf(-1.702f * gg0)) * (uu0 + 1.0f) * smv;
                d1[n] = gg1 / (1.0f + expf(-1.702f * gg1)) * (uu1 + 1.0f) * smv;
            }
        }
    }
}

// ---------------- GEMM2: IMMA m16n8k32, CTA 128m x 128n, K=2048 ----------------
// grid (16, 4, 16). 8 warps = 4m x 2n; warp tile 32m x 64n.
__global__ void __launch_bounds__(256) k_gemm2(const float* __restrict__ w2s,
                                               const float* __restrict__ w2b) {
    int e = blockIdx.z, mt = blockIdx.y, nt = blockIdx.x;
    int cnt = g_cnt[e];
    if (mt * 128 >= cnt) return;

    __shared__ int As[2][8 * 136];
    __shared__ int Bs[2][8 * 136];
    __shared__ float s_hs[128];
    __shared__ float s_zs[128], s_zb[128];

    int t = threadIdx.x;
    if (t < 128) {
        s_hs[t] = g_hs[e * CAP + mt * 128 + t];
        int n = nt * 128 + t;
        s_zs[t] = w2s[e * H_DIM + n];
        s_zb[t] = w2b[e * H_DIM + n];
    }
    __syncthreads();

    int lane = t & 31, wid = t >> 5;
    int wm = (wid & 3) * 32;
    int wn = (wid >> 2) * 64;
    int grp = lane >> 2, qid = lane & 3;

    int am = t >> 1, ajj = (t & 1) * 4;
    int bj = t >> 5, bn4 = t & 31;
    const int* aptr = g_hq + ((long long)e * CAP + mt * 128 + am) * 512 + ajj;
    const int* bptr = g_w2p + (long long)e * 512 * H_DIM + nt * 128 + bn4 * 4;

    int acc[2][8][4];
    #pragma unroll
    for (int i = 0; i < 2; i++)
        #pragma unroll
        for (int j = 0; j < 8; j++)
            #pragma unroll
            for (int k = 0; k < 4; k++) acc[i][j][k] = 0;

    {
        int4 av = *(const int4*)(aptr);
        As[0][(ajj + 0) * 136 + am] = av.x;
        As[0][(ajj + 1) * 136 + am] = av.y;
        As[0][(ajj + 2) * 136 + am] = av.z;
        As[0][(ajj + 3) * 136 + am] = av.w;
        int4 bv = *(const int4*)(bptr + (long long)bj * H_DIM);
        *(int4*)&Bs[0][bj * 136 + bn4 * 4] = bv;
    }
    __syncthreads();

    for (int kt = 0; kt < 64; kt++) {
        int buf = kt & 1;
        if (kt + 1 < 64) {
            int k4b = (kt + 1) * 8;
            int nb = buf ^ 1;
            int4 av = *(const int4*)(aptr + k4b);
            As[nb][(ajj + 0) * 136 + am] = av.x;
            As[nb][(ajj + 1) * 136 + am] = av.y;
            As[nb][(ajj + 2) * 136 + am] = av.z;
            As[nb][(ajj + 3) * 136 + am] = av.w;
            int4 bv = *(const int4*)(bptr + (long long)(k4b + bj) * H_DIM);
            *(int4*)&Bs[nb][bj * 136 + bn4 * 4] = bv;
        }
        int a[2][4];
        #pragma unroll
        for (int mf = 0; mf < 2; mf++) {
            int mr = wm + mf * 16 + grp;
            a[mf][0] = As[buf][qid * 136 + mr];
            a[mf][1] = As[buf][qid * 136 + mr + 8];
            a[mf][2] = As[buf][(qid + 4) * 136 + mr];
            a[mf][3] = As[buf][(qid + 4) * 136 + mr + 8];
        }
        #pragma unroll
        for (int nf = 0; nf < 8; nf++) {
            int cc = wn + nf * 8 + grp;
            int b[2] = { Bs[buf][qid * 136 + cc], Bs[buf][(qid + 4) * 136 + cc] };
            #pragma unroll
            for (int mf = 0; mf < 2; mf++)
                mma_s8(acc[mf][nf], a[mf], b);
        }
        __syncthreads();
    }

    #pragma unroll
    for (int mf = 0; mf < 2; mf++) {
        int r0 = wm + mf * 16 + grp;
        int r1 = r0 + 8;
        float hs0 = s_hs[r0], hs1 = s_hs[r1];
        float* d0 = g_z + ((size_t)e * CAP + mt * 128 + r0) * H_DIM + (size_t)nt * 128;
        float* d1 = g_z + ((size_t)e * CAP + mt * 128 + r1) * H_DIM + (size_t)nt * 128;
        #pragma unroll
        for (int nf = 0; nf < 8; nf++) {
            int nl = wn + nf * 8 + qid * 2;
            #pragma unroll
            for (int c = 0; c < 2; c++) {
                int n = nl + c;
                d0[n] = (float)acc[mf][nf][c]     * hs0 * s_zs[n] + s_zb[n];
                d1[n] = (float)acc[mf][nf][c + 2] * hs1 * s_zs[n] + s_zb[n];
            }
        }
    }
}

// ---------------- combine ----------------
__global__ void k_combine(float* __restrict__ out) {
    int tkn = blockIdx.x, t = threadIdx.x;
    int h0 = t * 8;
    float r[8] = {0, 0, 0, 0, 0, 0, 0, 0};
    #pragma unroll
    for (int k = 0; k < K_TOP; k++) {
        int sl = g_slot[tkn * K_TOP + k];
        if (sl >= 0) {
            float w = g_topk_w[tkn * K_TOP + k];
            const float4* zp = (const float4*)&g_z[(size_t)sl * H_DIM + h0];
            float4 z0 = zp[0], z1 = zp[1];
            r[0] += w * z0.x; r[1] += w * z0.y; r[2] += w * z0.z; r[3] += w * z0.w;
            r[4] += w * z1.x; r[5] += w * z1.y; r[6] += w * z1.z; r[7] += w * z1.w;
        }
    }
    float* op = out + (size_t)tkn * H_DIM + h0;
    *(float4*)op       = make_float4(r[0], r[1], r[2], r[3]);
    *(float4*)(op + 4) = make_float4(r[4], r[5], r[6], r[7]);
}

// ---------------- launch ----------------
extern "C" void kernel_launch(void* const* d_in, const int* in_sizes, int n_in,
                              void* d_out, int out_size) {
    const float* hidden = (const float*)d_in[0];
    const float* logits = (const float*)d_in[1];
    const float* w1     = (const float*)d_in[2];
    const float* w1s    = (const float*)d_in[3];
    const float* w1b    = (const float*)d_in[4];
    const float* smooth = (const float*)d_in[5];
    const float* w2     = (const float*)d_in[6];
    const float* w2s    = (const float*)d_in[7];
    const float* w2b    = (const float*)d_in[8];
    float* out = (float*)d_out;

    // repack weights to K-packed int8
    k_pack<<<32768, 256>>>(w1, 0, H_DIM, N1);
    k_pack<<<16384, 256>>>(w2, 1, I_DIM, H_DIM);

    // gating + token quant + routing
    k_gate<<<T_TOK, 32>>>(logits);
    k_quant<<<T_TOK, 256>>>(hidden, 0);
    k_route<<<1, 512>>>();

    // expert MLP on IMMA tensor cores
    k_gemm1<<<dim3(32, 4, E_EXP), 256>>>(w1s, w1b, smooth);
    k_quant<<<E_EXP * CAP, 256>>>(nullptr, 1);
    k_gemm2<<<dim3(16, 4, E_EXP), 256>>>(w2s, w2b);

    // weighted combine
    k_combine<<<T_TOK, 256>>>(out);
}

// round 15
// speedup vs baseline: 1.0151x; 1.0151x over previous
#include <cuda_runtime.h>
#include <stdint.h>
#include <math.h>

#define T_TOK 1024
#define E_EXP 16
#define K_TOP 4
#define H_DIM 2048
#define I_DIM 2048
#define CAP   512
#define N1    (2*I_DIM)   /* 4096 */

// ---------------- scratch (device globals; no runtime allocation) ----------------
__device__ int   g_w1p[E_EXP*(H_DIM/4)*N1];     // [E][K/4][2I] int32: byte j = k = 4*k4+j
__device__ int   g_w2p[E_EXP*(I_DIM/4)*H_DIM];  // [E][K/4][H]
__device__ int   g_xq[T_TOK*(H_DIM/4)];         // packed int8 tokens [T][512]
__device__ float g_xs[T_TOK];
__device__ int   g_topk_i[T_TOK*K_TOP];
__device__ float g_topk_w[T_TOK*K_TOP];
__device__ int   g_rowsrc[E_EXP*CAP];
__device__ int   g_slot[T_TOK*K_TOP];
__device__ int   g_cnt[E_EXP];
__device__ float g_act[(size_t)E_EXP*CAP*I_DIM];   // swiglu output
__device__ int   g_hq[E_EXP*CAP*(I_DIM/4)];        // requantized act
__device__ float g_hs[E_EXP*CAP];
__device__ float g_z[(size_t)E_EXP*CAP*H_DIM];     // GEMM2 output

// ---------------- helpers ----------------
__device__ __forceinline__ int packb(float a, float b, float c, float d) {
    return ( __float2int_rn(a) & 0xff)
         | ((__float2int_rn(b) & 0xff) << 8)
         | ((__float2int_rn(c) & 0xff) << 16)
         | ((__float2int_rn(d) & 0xff) << 24);
}
__device__ __forceinline__ int q8c(float v, float s) {
    int q = __float2int_rn(v / s);
    q = max(-127, min(127, q));
    return q & 0xff;
}
#define CP16(dst, src) asm volatile("cp.async.cg.shared.global [%0], [%1], 16;" :: "r"(dst), "l"(src))
#define CPCOMMIT()     asm volatile("cp.async.commit_group;" ::: "memory")
#define CPWAIT0()      asm volatile("cp.async.wait_group 0;" ::: "memory")

// ---------------- weight repack: f32 (int values) -> K-packed int8 ----------------
__global__ void k_pack(const float* __restrict__ in, int which, int Kd, int Nd) {
    int* __restrict__ out = which ? g_w2p : g_w1p;
    long long i4  = (long long)blockIdx.x * blockDim.x + threadIdx.x;
    long long lin = i4 * 4;
    long long perE = (long long)(Kd >> 2) * Nd;
    int e  = (int)(lin / perE);
    long long rem = lin - (long long)e * perE;
    int k4 = (int)(rem / Nd);
    int n  = (int)(rem - (long long)k4 * Nd);
    const float* p = in + ((long long)e * Kd + 4 * k4) * Nd + n;
    float4 r0 = *(const float4*)(p);
    float4 r1 = *(const float4*)(p + Nd);
    float4 r2 = *(const float4*)(p + 2 * Nd);
    float4 r3 = *(const float4*)(p + 3 * Nd);
    int4 o;
    o.x = packb(r0.x, r1.x, r2.x, r3.x);
    o.y = packb(r0.y, r1.y, r2.y, r3.y);
    o.z = packb(r0.z, r1.z, r2.z, r3.z);
    o.w = packb(r0.w, r1.w, r2.w, r3.w);
    *(int4*)(out + lin) = o;
}

// ---------------- gating: softmax + top-4 + renormalize ----------------
__global__ void k_gate(const float* __restrict__ logits) {
    int t = blockIdx.x, lane = threadIdx.x;
    float v = (lane < E_EXP) ? logits[t * E_EXP + lane] : -1e30f;
    float m = v;
    #pragma unroll
    for (int o = 16; o; o >>= 1) m = fmaxf(m, __shfl_xor_sync(0xffffffffu, m, o));
    float cur = (lane < E_EXP) ? expf(v - m) : -1.0f;
    float w[K_TOP]; int id[K_TOP];
    #pragma unroll
    for (int k = 0; k < K_TOP; k++) {
        float bv = cur; int bi = lane;
        #pragma unroll
        for (int o = 16; o; o >>= 1) {
            float ov = __shfl_xor_sync(0xffffffffu, bv, o);
            int   oi = __shfl_xor_sync(0xffffffffu, bi, o);
            if (ov > bv || (ov == bv && oi < bi)) { bv = ov; bi = oi; }
        }
        w[k] = bv; id[k] = bi;
        if (lane == bi) cur = -1.0f;
    }
    float s = w[0] + w[1] + w[2] + w[3];
    if (lane < K_TOP) {
        g_topk_i[t * K_TOP + lane] = id[lane];
        g_topk_w[t * K_TOP + lane] = w[lane] / s;
    }
}

// ---------------- per-row dynamic int8 quant ----------------
__global__ void k_quant(const float* __restrict__ xin, int which) {
    const float* x; int* q; float* s;
    if (which == 0) { x = xin;  q = g_xq; s = g_xs; }
    else            { x = g_act; q = g_hq; s = g_hs; }
    int r = blockIdx.x, t = threadIdx.x;
    const float* row = x + (long long)r * 2048;
    float4 a = *(const float4*)(row + t * 8);
    float4 b = *(const float4*)(row + t * 8 + 4);
    float mx = fmaxf(fmaxf(fmaxf(fabsf(a.x), fabsf(a.y)), fmaxf(fabsf(a.z), fabsf(a.w))),
                     fmaxf(fmaxf(fabsf(b.x), fabsf(b.y)), fmaxf(fabsf(b.z), fabsf(b.w))));
    __shared__ float sm[256];
    sm[t] = mx; __syncthreads();
    #pragma unroll
    for (int o = 128; o; o >>= 1) { if (t < o) sm[t] = fmaxf(sm[t], sm[t + o]); __syncthreads(); }
    float scale = fmaxf(sm[0] / 127.0f, 1e-8f);
    int2 o2;
    o2.x = q8c(a.x, scale) | (q8c(a.y, scale) << 8) | (q8c(a.z, scale) << 16) | (q8c(a.w, scale) << 24);
    o2.y = q8c(b.x, scale) | (q8c(b.y, scale) << 8) | (q8c(b.z, scale) << 16) | (q8c(b.w, scale) << 24);
    *(int2*)(q + (long long)r * 512 + t * 2) = o2;
    if (t == 0) s[r] = scale;
}

// ---------------- routing ----------------
__global__ void k_route() {
    int w = threadIdx.x >> 5, lane = threadIdx.x & 31;
    int base = 0;
    for (int c = 0; c < (T_TOK * K_TOP) / 32; c++) {
        int i = c * 32 + lane;
        int e = g_topk_i[i];
        unsigned mask = __ballot_sync(0xffffffffu, e == w);
        if (e == w) {
            int pos = base + __popc(mask & ((1u << lane) - 1u));
            if (pos < CAP) { g_rowsrc[w * CAP + pos] = i >> 2; g_slot[i] = w * CAP + pos; }
            else           { g_slot[i] = -1; }
        }
        base += __popc(mask);
    }
    int cnt = min(base, CAP);
    if (lane == 0) g_cnt[w] = cnt;
    for (int p = cnt + lane; p < CAP; p += 32) g_rowsrc[w * CAP + p] = -1;
}

// ======================================================================
// GEMM1: dp4a, CTA 128m x (64 gate + 64 up), K=2048, BK=64B (16 k4)
// 8 warps = 2m x 4n; thread tile 8m x (4 gate + 4 up) = 64 dp4a / k4
// grid (32, 4, 16)
// ======================================================================
__global__ void __launch_bounds__(256, 2) k_gemm1(const float* __restrict__ w1s,
                                                  const float* __restrict__ w1b,
                                                  const float* __restrict__ smooth) {
    int e = blockIdx.z, mt = blockIdx.y, ng = blockIdx.x;
    int cnt = g_cnt[e];
    if (mt * 128 >= cnt) return;

    __shared__ int As[2][16][132];    // [buf][k4][m]
    __shared__ int Bs[2][16][136];    // [buf][k4][cc] cc<64 gate, cc>=64 up
    __shared__ int s_src[128];
    __shared__ float s_xs[128];
    __shared__ float s_gs[64], s_gb[64], s_us[64], s_ub[64], s_sm[64];

    int t = threadIdx.x;
    if (t < 128) {
        int s = g_rowsrc[e * CAP + mt * 128 + t];
        s_src[t] = s;
        s_xs[t] = (s >= 0) ? g_xs[s] : 0.0f;
    }
    if (t < 64) {
        int n = ng * 64 + t;
        s_gs[t] = w1s[e * N1 + n];
        s_gb[t] = w1b[e * N1 + n];
        s_us[t] = w1s[e * N1 + I_DIM + n];
        s_ub[t] = w1b[e * N1 + I_DIM + n];
        s_sm[t] = smooth[e * I_DIM + n];
    }
    __syncthreads();

    // ---- staging indices ----
    int am = t & 127, ah = t >> 7;                  // A: row am, 8-int half ah
    int asrc = s_src[am];
    const int* aptr = (asrc >= 0) ? (g_xq + asrc * 512 + ah * 8) : (const int*)0;
    int bk = t >> 4, bc = (t & 15) * 8;             // B: k4-row bk, 8-col chunk bc
    long long bn = (bc < 64) ? (long long)(ng * 64 + bc)
                             : (long long)(I_DIM + ng * 64 + (bc - 64));
    const int* bptr = g_w1p + (long long)e * 512 * N1 + bn;

    // ---- compute indices ----
    int lane = t & 31, wid = t >> 5;
    int m0 = (wid & 1) * 64 + (lane >> 2) * 8;      // 8 rows
    int cg = (wid >> 1) * 16 + (lane & 3) * 4;      // 4 gate cols (up = +64)

    int accg[8][4], accu[8][4];
    #pragma unroll
    for (int i = 0; i < 8; i++)
        #pragma unroll
        for (int j = 0; j < 4; j++) { accg[i][j] = 0; accu[i][j] = 0; }

    // prologue: stage 0 into buf 0
    {
        uint32_t bd = (uint32_t)__cvta_generic_to_shared(&Bs[0][bk][bc]);
        CP16(bd, bptr + (long long)bk * N1);
        CP16(bd + 16, bptr + (long long)bk * N1 + 4);
        CPCOMMIT();
        int4 a0 = aptr ? *(const int4*)(aptr) : make_int4(0,0,0,0);
        int4 a1 = aptr ? *(const int4*)(aptr + 4) : make_int4(0,0,0,0);
        int kb = ah * 8;
        As[0][kb+0][am]=a0.x; As[0][kb+1][am]=a0.y; As[0][kb+2][am]=a0.z; As[0][kb+3][am]=a0.w;
        As[0][kb+4][am]=a1.x; As[0][kb+5][am]=a1.y; As[0][kb+6][am]=a1.z; As[0][kb+7][am]=a1.w;
        CPWAIT0();
    }
    __syncthreads();

    for (int s = 0; s < 32; s++) {
        int p = s & 1;
        int4 na0, na1;
        bool pre = (s + 1 < 32);
        if (pre) {
            int k0n = (s + 1) * 16;
            uint32_t bd = (uint32_t)__cvta_generic_to_shared(&Bs[p ^ 1][bk][bc]);
            CP16(bd, bptr + (long long)(k0n + bk) * N1);
            CP16(bd + 16, bptr + (long long)(k0n + bk) * N1 + 4);
            CPCOMMIT();
            na0 = aptr ? *(const int4*)(aptr + k0n) : make_int4(0,0,0,0);
            na1 = aptr ? *(const int4*)(aptr + k0n + 4) : make_int4(0,0,0,0);
        }
        #pragma unroll 4
        for (int k4 = 0; k4 < 16; k4++) {
            int4 a0 = *(const int4*)&As[p][k4][m0];
            int4 a1 = *(const int4*)&As[p][k4][m0 + 4];
            int4 bgv = *(const int4*)&Bs[p][k4][cg];
            int4 buv = *(const int4*)&Bs[p][k4][64 + cg];
            int a[8] = {a0.x,a0.y,a0.z,a0.w,a1.x,a1.y,a1.z,a1.w};
            int bg[4] = {bgv.x,bgv.y,bgv.z,bgv.w};
            int bu[4] = {buv.x,buv.y,buv.z,buv.w};
            #pragma unroll
            for (int i = 0; i < 8; i++)
                #pragma unroll
                for (int j = 0; j < 4; j++) {
                    accg[i][j] = __dp4a(a[i], bg[j], accg[i][j]);
                    accu[i][j] = __dp4a(a[i], bu[j], accu[i][j]);
                }
        }
        if (pre) {
            int kb = ah * 8, pb = p ^ 1;
            As[pb][kb+0][am]=na0.x; As[pb][kb+1][am]=na0.y; As[pb][kb+2][am]=na0.z; As[pb][kb+3][am]=na0.w;
            As[pb][kb+4][am]=na1.x; As[pb][kb+5][am]=na1.y; As[pb][kb+6][am]=na1.z; As[pb][kb+7][am]=na1.w;
        }
        CPWAIT0();
        __syncthreads();
    }

    // epilogue: dequant + swiglu, write g_act
    #pragma unroll
    for (int i = 0; i < 8; i++) {
        int m = m0 + i;
        float xs = s_xs[m];
        float* dst = g_act + ((size_t)e * CAP + mt * 128 + m) * I_DIM + (size_t)ng * 64 + cg;
        float4 res;
        #pragma unroll
        for (int j = 0; j < 4; j++) {
            int n = cg + j;
            float yg = (float)accg[i][j] * xs * s_gs[n] + s_gb[n];
            float yu = (float)accu[i][j] * xs * s_us[n] + s_ub[n];
            float gg = fminf(yg, 7.0f);
            float uu = fminf(fmaxf(yu, -7.0f), 7.0f);
            ((float*)&res)[j] = gg / (1.0f + expf(-1.702f * gg)) * (uu + 1.0f) * s_sm[n];
        }
        *(float4*)dst = res;
    }
}

// ======================================================================
// GEMM2: dp4a, CTA 128m x 128n, K=2048, BK=64B; thread tile 8m x 8n
// grid (16, 4, 16)
// ======================================================================
__global__ void __launch_bounds__(256, 2) k_gemm2(const float* __restrict__ w2s,
                                                  const float* __restrict__ w2b) {
    int e = blockIdx.z, mt = blockIdx.y, nt = blockIdx.x;
    int cnt = g_cnt[e];
    if (mt * 128 >= cnt) return;

    __shared__ int As[2][16][132];
    __shared__ int Bs[2][16][136];
    __shared__ float s_hs[128];
    __shared__ float s_zs[128], s_zb[128];

    int t = threadIdx.x;
    if (t < 128) {
        s_hs[t] = g_hs[e * CAP + mt * 128 + t];
        int n = nt * 128 + t;
        s_zs[t] = w2s[e * H_DIM + n];
        s_zb[t] = w2b[e * H_DIM + n];
    }
    __syncthreads();

    int am = t & 127, ah = t >> 7;
    const int* aptr = g_hq + ((long long)e * CAP + mt * 128 + am) * 512 + ah * 8;
    int bk = t >> 4, bc = (t & 15) * 8;
    const int* bptr = g_w2p + (long long)e * 512 * H_DIM + nt * 128 + bc;

    int lane = t & 31, wid = t >> 5;
    int m0 = (wid & 1) * 64 + (lane >> 2) * 8;
    int cn = (wid >> 1) * 32 + (lane & 3) * 8;      // 8 cols

    int acc[8][8];
    #pragma unroll
    for (int i = 0; i < 8; i++)
        #pragma unroll
        for (int j = 0; j < 8; j++) acc[i][j] = 0;

    {
        uint32_t bd = (uint32_t)__cvta_generic_to_shared(&Bs[0][bk][bc]);
        CP16(bd, bptr + (long long)bk * H_DIM);
        CP16(bd + 16, bptr + (long long)bk * H_DIM + 4);
        CPCOMMIT();
        int4 a0 = *(const int4*)(aptr);
        int4 a1 = *(const int4*)(aptr + 4);
        int kb = ah * 8;
        As[0][kb+0][am]=a0.x; As[0][kb+1][am]=a0.y; As[0][kb+2][am]=a0.z; As[0][kb+3][am]=a0.w;
        As[0][kb+4][am]=a1.x; As[0][kb+5][am]=a1.y; As[0][kb+6][am]=a1.z; As[0][kb+7][am]=a1.w;
        CPWAIT0();
    }
    __syncthreads();

    for (int s = 0; s < 32; s++) {
        int p = s & 1;
        int4 na0, na1;
        bool pre = (s + 1 < 32);
        if (pre) {
            int k0n = (s + 1) * 16;
            uint32_t bd = (uint32_t)__cvta_generic_to_shared(&Bs[p ^ 1][bk][bc]);
            CP16(bd, bptr + (long long)(k0n + bk) * H_DIM);
            CP16(bd + 16, bptr + (long long)(k0n + bk) * H_DIM + 4);
            CPCOMMIT();
            na0 = *(const int4*)(aptr + k0n);
            na1 = *(const int4*)(aptr + k0n + 4);
        }
        #pragma unroll 4
        for (int k4 = 0; k4 < 16; k4++) {
            int4 a0 = *(const int4*)&As[p][k4][m0];
            int4 a1 = *(const int4*)&As[p][k4][m0 + 4];
            int4 b0 = *(const int4*)&Bs[p][k4][cn];
            int4 b1 = *(const int4*)&Bs[p][k4][cn + 4];
            int a[8] = {a0.x,a0.y,a0.z,a0.w,a1.x,a1.y,a1.z,a1.w};
            int b[8] = {b0.x,b0.y,b0.z,b0.w,b1.x,b1.y,b1.z,b1.w};
            #pragma unroll
            for (int i = 0; i < 8; i++)
                #pragma unroll
                for (int j = 0; j < 8; j++)
                    acc[i][j] = __dp4a(a[i], b[j], acc[i][j]);
        }
        if (pre) {
            int kb = ah * 8, pb = p ^ 1;
            As[pb][kb+0][am]=na0.x; As[pb][kb+1][am]=na0.y; As[pb][kb+2][am]=na0.z; As[pb][kb+3][am]=na0.w;
            As[pb][kb+4][am]=na1.x; As[pb][kb+5][am]=na1.y; As[pb][kb+6][am]=na1.z; As[pb][kb+7][am]=na1.w;
        }
        CPWAIT0();
        __syncthreads();
    }

    #pragma unroll
    for (int i = 0; i < 8; i++) {
        int m = m0 + i;
        float hs = s_hs[m];
        float* dst = g_z + ((size_t)e * CAP + mt * 128 + m) * H_DIM + (size_t)nt * 128 + cn;
        float4 r0, r1;
        #pragma unroll
        for (int j = 0; j < 8; j++) {
            int n = cn + j;
            float z = (float)acc[i][j] * hs * s_zs[n] + s_zb[n];
            if (j < 4) ((float*)&r0)[j] = z; else ((float*)&r1)[j - 4] = z;
        }
        *(float4*)dst = r0;
        *(float4*)(dst + 4) = r1;
    }
}

// ---------------- combine ----------------
__global__ void k_combine(float* __restrict__ out) {
    int tkn = blockIdx.x, t = threadIdx.x;
    int h0 = t * 8;
    float r[8] = {0, 0, 0, 0, 0, 0, 0, 0};
    #pragma unroll
    for (int k = 0; k < K_TOP; k++) {
        int sl = g_slot[tkn * K_TOP + k];
        if (sl >= 0) {
            float w = g_topk_w[tkn * K_TOP + k];
            const float4* zp = (const float4*)&g_z[(size_t)sl * H_DIM + h0];
            float4 z0 = zp[0], z1 = zp[1];
            r[0] += w * z0.x; r[1] += w * z0.y; r[2] += w * z0.z; r[3] += w * z0.w;
            r[4] += w * z1.x; r[5] += w * z1.y; r[6] += w * z1.z; r[7] += w * z1.w;
        }
    }
    float* op = out + (size_t)tkn * H_DIM + h0;
    *(float4*)op       = make_float4(r[0], r[1], r[2], r[3]);
    *(float4*)(op + 4) = make_float4(r[4], r[5], r[6], r[7]);
}

// ---------------- launch ----------------
extern "C" void kernel_launch(void* const* d_in, const int* in_sizes, int n_in,
                              void* d_out, int out_size) {
    const float* hidden = (const float*)d_in[0];
    const float* logits = (const float*)d_in[1];
    const float* w1     = (const float*)d_in[2];
    const float* w1s    = (const float*)d_in[3];
    const float* w1b    = (const float*)d_in[4];
    const float* smooth = (const float*)d_in[5];
    const float* w2     = (const float*)d_in[6];
    const float* w2s    = (const float*)d_in[7];
    const float* w2b    = (const float*)d_in[8];
    float* out = (float*)d_out;

    // repack weights to K-packed int8
    k_pack<<<32768, 256>>>(w1, 0, H_DIM, N1);
    k_pack<<<16384, 256>>>(w2, 1, I_DIM, H_DIM);

    // gating + token quant + routing
    k_gate<<<T_TOK, 32>>>(logits);
    k_quant<<<T_TOK, 256>>>(hidden, 0);
    k_route<<<1, 512>>>();

    // expert MLP (dp4a, register-tiled, cp.async pipelined)
    k_gemm1<<<dim3(32, 4, E_EXP), 256>>>(w1s, w1b, smooth);
    k_quant<<<E_EXP * CAP, 256>>>(nullptr, 1);
    k_gemm2<<<dim3(16, 4, E_EXP), 256>>>(w2s, w2b);

    // weighted combine
    k_combine<<<T_TOK, 256>>>(out);
}

// round 16
// speedup vs baseline: 1.1718x; 1.1543x over previous
#include <cuda_runtime.h>
#include <stdint.h>
#include <math.h>

#define T_TOK 1024
#define E_EXP 16
#define K_TOP 4
#define H_DIM 2048
#define I_DIM 2048
#define CAP   512
#define N1    (2*I_DIM)   /* 4096 */

// ---------------- scratch (device globals; no runtime allocation) ----------------
__device__ int   g_w1p[E_EXP*(H_DIM/4)*N1];     // [E][K/4][2I] int32: byte j = k = 4*k4+j
__device__ int   g_w2p[E_EXP*(I_DIM/4)*H_DIM];  // [E][K/4][H]
__device__ int   g_xq[T_TOK*(H_DIM/4)];         // packed int8 tokens [T][512]
__device__ float g_xs[T_TOK];
__device__ int   g_topk_i[T_TOK*K_TOP];
__device__ float g_topk_w[T_TOK*K_TOP];
__device__ int   g_rowsrc[E_EXP*CAP];
__device__ int   g_slot[T_TOK*K_TOP];
__device__ int   g_cnt[E_EXP];
__device__ float g_act[(size_t)E_EXP*CAP*I_DIM];   // swiglu output
__device__ int   g_hq[E_EXP*CAP*(I_DIM/4)];        // requantized act
__device__ float g_hs[E_EXP*CAP];
__device__ float g_z[(size_t)E_EXP*CAP*H_DIM];     // GEMM2 output

// ---------------- helpers ----------------
__device__ __forceinline__ int packb(float a, float b, float c, float d) {
    return ( __float2int_rn(a) & 0xff)
         | ((__float2int_rn(b) & 0xff) << 8)
         | ((__float2int_rn(c) & 0xff) << 16)
         | ((__float2int_rn(d) & 0xff) << 24);
}
__device__ __forceinline__ int q8c(float v, float s) {
    int q = __float2int_rn(v / s);
    q = max(-127, min(127, q));
    return q & 0xff;
}
#define CP16(dst, src) asm volatile("cp.async.cg.shared.global [%0], [%1], 16;" :: "r"(dst), "l"(src))
#define CPCOMMIT()     asm volatile("cp.async.commit_group;" ::: "memory")
#define CPWAIT0()      asm volatile("cp.async.wait_group 0;" ::: "memory")

// ---------------- fused weight repack: f32 (int values) -> K-packed int8 ----------------
// blocks [0, 32768): w1 ; [32768, 49152): w2
__global__ void k_pack_all(const float* __restrict__ w1, const float* __restrict__ w2) {
    int which = (blockIdx.x >= 32768);
    const float* in = which ? w2 : w1;
    int* __restrict__ out = which ? g_w2p : g_w1p;
    int Nd = which ? H_DIM : N1;
    long long blk = which ? (blockIdx.x - 32768) : blockIdx.x;
    long long i4  = blk * blockDim.x + threadIdx.x;
    long long lin = i4 * 4;
    long long perE = (long long)512 * Nd;       // (Kd/4)*Nd, Kd=2048 both
    int e  = (int)(lin / perE);
    long long rem = lin - (long long)e * perE;
    int k4 = (int)(rem / Nd);
    int n  = (int)(rem - (long long)k4 * Nd);
    const float* p = in + ((long long)e * 2048 + 4 * k4) * Nd + n;
    float4 r0 = *(const float4*)(p);
    float4 r1 = *(const float4*)(p + Nd);
    float4 r2 = *(const float4*)(p + 2 * Nd);
    float4 r3 = *(const float4*)(p + 3 * Nd);
    int4 o;
    o.x = packb(r0.x, r1.x, r2.x, r3.x);
    o.y = packb(r0.y, r1.y, r2.y, r3.y);
    o.z = packb(r0.z, r1.z, r2.z, r3.z);
    o.w = packb(r0.w, r1.w, r2.w, r3.w);
    *(int4*)(out + lin) = o;
}

// ---------------- per-row dynamic int8 quant ----------------
__global__ void k_quant(const float* __restrict__ xin, int which) {
    const float* x; int* q; float* s;
    if (which == 0) { x = xin;  q = g_xq; s = g_xs; }
    else            { x = g_act; q = g_hq; s = g_hs; }
    int r = blockIdx.x, t = threadIdx.x;
    const float* row = x + (long long)r * 2048;
    float4 a = *(const float4*)(row + t * 8);
    float4 b = *(const float4*)(row + t * 8 + 4);
    float mx = fmaxf(fmaxf(fmaxf(fabsf(a.x), fabsf(a.y)), fmaxf(fabsf(a.z), fabsf(a.w))),
                     fmaxf(fmaxf(fabsf(b.x), fabsf(b.y)), fmaxf(fabsf(b.z), fabsf(b.w))));
    __shared__ float sm[256];
    sm[t] = mx; __syncthreads();
    #pragma unroll
    for (int o = 128; o; o >>= 1) { if (t < o) sm[t] = fmaxf(sm[t], sm[t + o]); __syncthreads(); }
    float scale = fmaxf(sm[0] / 127.0f, 1e-8f);
    int2 o2;
    o2.x = q8c(a.x, scale) | (q8c(a.y, scale) << 8) | (q8c(a.z, scale) << 16) | (q8c(a.w, scale) << 24);
    o2.y = q8c(b.x, scale) | (q8c(b.y, scale) << 8) | (q8c(b.z, scale) << 16) | (q8c(b.w, scale) << 24);
    *(int2*)(q + (long long)r * 512 + t * 2) = o2;
    if (t == 0) s[r] = scale;
}

// ---------------- fused gating (softmax+top4+renorm) + routing; 1 block, 1024 threads ----------------
__global__ void k_gateroute(const float* __restrict__ logits) {
    int t = threadIdx.x, warp = t >> 5, lane = t & 31;

    // phase 1: gating — warp w handles tokens w, w+32, ...
    for (int tok = warp; tok < T_TOK; tok += 32) {
        float v = (lane < E_EXP) ? logits[tok * E_EXP + lane] : -1e30f;
        float m = v;
        #pragma unroll
        for (int o = 16; o; o >>= 1) m = fmaxf(m, __shfl_xor_sync(0xffffffffu, m, o));
        float cur = (lane < E_EXP) ? expf(v - m) : -1.0f;
        float w[K_TOP]; int id[K_TOP];
        #pragma unroll
        for (int k = 0; k < K_TOP; k++) {
            float bv = cur; int bi = lane;
            #pragma unroll
            for (int o = 16; o; o >>= 1) {
                float ov = __shfl_xor_sync(0xffffffffu, bv, o);
                int   oi = __shfl_xor_sync(0xffffffffu, bi, o);
                if (ov > bv || (ov == bv && oi < bi)) { bv = ov; bi = oi; }
            }
            w[k] = bv; id[k] = bi;
            if (lane == bi) cur = -1.0f;
        }
        float s = w[0] + w[1] + w[2] + w[3];
        if (lane < K_TOP) {
            g_topk_i[tok * K_TOP + lane] = id[lane];
            g_topk_w[tok * K_TOP + lane] = w[lane] / s;
        }
    }
    __syncthreads();

    // phase 2: routing — warps 0..15, warp = expert
    if (t < 512) {
        int w = warp;
        int base = 0;
        for (int c = 0; c < (T_TOK * K_TOP) / 32; c++) {
            int i = c * 32 + lane;
            int e = g_topk_i[i];
            unsigned mask = __ballot_sync(0xffffffffu, e == w);
            if (e == w) {
                int pos = base + __popc(mask & ((1u << lane) - 1u));
                if (pos < CAP) { g_rowsrc[w * CAP + pos] = i >> 2; g_slot[i] = w * CAP + pos; }
                else           { g_slot[i] = -1; }
            }
            base += __popc(mask);
        }
        int cnt = min(base, CAP);
        if (lane == 0) g_cnt[w] = cnt;
        for (int p = cnt + lane; p < CAP; p += 32) g_rowsrc[w * CAP + p] = -1;
    }
}

// ======================================================================
// GEMM1: dp4a, CTA 64m x (64 gate + 64 up), K=2048, BK=64B (16 k4)
// 128 threads = 4 warps (2m x 2n); thread tile 8m x (4+4)n = 64 dp4a / k4
// grid (32, 8, 16); 4 CTAs/SM -> 4 warps/SMSP -> dp4a pipe-bound
// ======================================================================
__global__ void __launch_bounds__(128, 4) k_gemm1(const float* __restrict__ w1s,
                                                  const float* __restrict__ w1b,
                                                  const float* __restrict__ smooth) {
    int e = blockIdx.z, mt = blockIdx.y, ng = blockIdx.x;
    int cnt = g_cnt[e];
    if (mt * 64 >= cnt) return;

    __shared__ int As[2][16][68];     // [buf][k4][m]
    __shared__ int Bs[2][16][136];    // [buf][k4][cc] cc<64 gate, cc>=64 up
    __shared__ int s_src[64];
    __shared__ float s_xs[64];
    __shared__ float s_gs[64], s_gb[64], s_us[64], s_ub[64], s_sm[64];

    int t = threadIdx.x;
    if (t < 64) {
        int s = g_rowsrc[e * CAP + mt * 64 + t];
        s_src[t] = s;
        s_xs[t] = (s >= 0) ? g_xs[s] : 0.0f;
        int n = ng * 64 + t;
        s_gs[t] = w1s[e * N1 + n];
        s_gb[t] = w1b[e * N1 + n];
        s_us[t] = w1s[e * N1 + I_DIM + n];
        s_ub[t] = w1b[e * N1 + I_DIM + n];
        s_sm[t] = smooth[e * I_DIM + n];
    }
    __syncthreads();

    // staging indices
    int am = t >> 1, ah = t & 1;                   // A: row am, 8-int half ah
    int asrc = s_src[am];
    const int* aptr = (asrc >= 0) ? (g_xq + asrc * 512 + ah * 8) : (const int*)0;
    int bk = t >> 3, bc = (t & 7) * 16;            // B: k4-row bk, 16-col chunk bc
    long long bn = (bc < 64) ? (long long)(ng * 64 + bc)
                             : (long long)(I_DIM + ng * 64 + (bc - 64));
    const int* bptr = g_w1p + (long long)e * 512 * N1 + bn;

    // compute indices
    int lane = t & 31, wid = t >> 5;
    int m0 = (wid & 1) * 32 + (lane >> 3) * 8;     // 8 rows
    int cg = (wid >> 1) * 32 + (lane & 7) * 4;     // 4 gate cols (up = +64)

    int accg[8][4], accu[8][4];
    #pragma unroll
    for (int i = 0; i < 8; i++)
        #pragma unroll
        for (int j = 0; j < 4; j++) { accg[i][j] = 0; accu[i][j] = 0; }

    // prologue: stage chunk 0 into buf 0
    {
        uint32_t bd = (uint32_t)__cvta_generic_to_shared(&Bs[0][bk][bc]);
        const int* bsrc = bptr + (long long)bk * N1;
        CP16(bd, bsrc); CP16(bd + 16, bsrc + 4); CP16(bd + 32, bsrc + 8); CP16(bd + 48, bsrc + 12);
        CPCOMMIT();
        int4 a0 = aptr ? *(const int4*)(aptr) : make_int4(0,0,0,0);
        int4 a1 = aptr ? *(const int4*)(aptr + 4) : make_int4(0,0,0,0);
        int kb = ah * 8;
        As[0][kb+0][am]=a0.x; As[0][kb+1][am]=a0.y; As[0][kb+2][am]=a0.z; As[0][kb+3][am]=a0.w;
        As[0][kb+4][am]=a1.x; As[0][kb+5][am]=a1.y; As[0][kb+6][am]=a1.z; As[0][kb+7][am]=a1.w;
        CPWAIT0();
    }
    __syncthreads();

    for (int s = 0; s < 32; s++) {
        int p = s & 1;
        int4 na0, na1;
        bool pre = (s + 1 < 32);
        if (pre) {
            int k0n = (s + 1) * 16;
            uint32_t bd = (uint32_t)__cvta_generic_to_shared(&Bs[p ^ 1][bk][bc]);
            const int* bsrc = bptr + (long long)(k0n + bk) * N1;
            CP16(bd, bsrc); CP16(bd + 16, bsrc + 4); CP16(bd + 32, bsrc + 8); CP16(bd + 48, bsrc + 12);
            CPCOMMIT();
            na0 = aptr ? *(const int4*)(aptr + k0n) : make_int4(0,0,0,0);
            na1 = aptr ? *(const int4*)(aptr + k0n + 4) : make_int4(0,0,0,0);
        }
        #pragma unroll
        for (int k4 = 0; k4 < 16; k4++) {
            int4 a0 = *(const int4*)&As[p][k4][m0];
            int4 a1 = *(const int4*)&As[p][k4][m0 + 4];
            int4 bgv = *(const int4*)&Bs[p][k4][cg];
            int4 buv = *(const int4*)&Bs[p][k4][64 + cg];
            int a[8] = {a0.x,a0.y,a0.z,a0.w,a1.x,a1.y,a1.z,a1.w};
            int bg[4] = {bgv.x,bgv.y,bgv.z,bgv.w};
            int bu[4] = {buv.x,buv.y,buv.z,buv.w};
            #pragma unroll
            for (int i = 0; i < 8; i++)
                #pragma unroll
                for (int j = 0; j < 4; j++) {
                    accg[i][j] = __dp4a(a[i], bg[j], accg[i][j]);
                    accu[i][j] = __dp4a(a[i], bu[j], accu[i][j]);
                }
        }
        if (pre) {
            int kb = ah * 8, pb = p ^ 1;
            As[pb][kb+0][am]=na0.x; As[pb][kb+1][am]=na0.y; As[pb][kb+2][am]=na0.z; As[pb][kb+3][am]=na0.w;
            As[pb][kb+4][am]=na1.x; As[pb][kb+5][am]=na1.y; As[pb][kb+6][am]=na1.z; As[pb][kb+7][am]=na1.w;
        }
        CPWAIT0();
        __syncthreads();
    }

    // epilogue: dequant + swiglu, write g_act
    #pragma unroll
    for (int i = 0; i < 8; i++) {
        int m = m0 + i;
        float xs = s_xs[m];
        float* dst = g_act + ((size_t)e * CAP + mt * 64 + m) * I_DIM + (size_t)ng * 64 + cg;
        float4 res;
        #pragma unroll
        for (int j = 0; j < 4; j++) {
            int n = cg + j;
            float yg = (float)accg[i][j] * xs * s_gs[n] + s_gb[n];
            float yu = (float)accu[i][j] * xs * s_us[n] + s_ub[n];
            float gg = fminf(yg, 7.0f);
            float uu = fminf(fmaxf(yu, -7.0f), 7.0f);
            ((float*)&res)[j] = gg / (1.0f + expf(-1.702f * gg)) * (uu + 1.0f) * s_sm[n];
        }
        *(float4*)dst = res;
    }
}

// ======================================================================
// GEMM2: dp4a, CTA 64m x 128n, K=2048, BK=64B; 128 threads, thread tile 8x8
// grid (16, 8, 16)
// ======================================================================
__global__ void __launch_bounds__(128, 4) k_gemm2(const float* __restrict__ w2s,
                                                  const float* __restrict__ w2b) {
    int e = blockIdx.z, mt = blockIdx.y, nt = blockIdx.x;
    int cnt = g_cnt[e];
    if (mt * 64 >= cnt) return;

    __shared__ int As[2][16][68];
    __shared__ int Bs[2][16][136];
    __shared__ float s_hs[64];
    __shared__ float s_zs[128], s_zb[128];

    int t = threadIdx.x;
    if (t < 64) s_hs[t] = g_hs[e * CAP + mt * 64 + t];
    {
        int n = nt * 128 + t;
        s_zs[t] = w2s[e * H_DIM + n];
        s_zb[t] = w2b[e * H_DIM + n];
    }
    __syncthreads();

    int am = t >> 1, ah = t & 1;
    const int* aptr = g_hq + ((long long)e * CAP + mt * 64 + am) * 512 + ah * 8;
    int bk = t >> 3, bc = (t & 7) * 16;
    const int* bptr = g_w2p + (long long)e * 512 * H_DIM + nt * 128 + bc;

    int lane = t & 31, wid = t >> 5;
    int m0 = (wid & 1) * 32 + (lane >> 3) * 8;
    int n0 = (wid >> 1) * 64 + (lane & 7) * 8;

    int acc[8][8];
    #pragma unroll
    for (int i = 0; i < 8; i++)
        #pragma unroll
        for (int j = 0; j < 8; j++) acc[i][j] = 0;

    {
        uint32_t bd = (uint32_t)__cvta_generic_to_shared(&Bs[0][bk][bc]);
        const int* bsrc = bptr + (long long)bk * H_DIM;
        CP16(bd, bsrc); CP16(bd + 16, bsrc + 4); CP16(bd + 32, bsrc + 8); CP16(bd + 48, bsrc + 12);
        CPCOMMIT();
        int4 a0 = *(const int4*)(aptr);
        int4 a1 = *(const int4*)(aptr + 4);
        int kb = ah * 8;
        As[0][kb+0][am]=a0.x; As[0][kb+1][am]=a0.y; As[0][kb+2][am]=a0.z; As[0][kb+3][am]=a0.w;
        As[0][kb+4][am]=a1.x; As[0][kb+5][am]=a1.y; As[0][kb+6][am]=a1.z; As[0][kb+7][am]=a1.w;
        CPWAIT0();
    }
    __syncthreads();

    for (int s = 0; s < 32; s++) {
        int p = s & 1;
        int4 na0, na1;
        bool pre = (s + 1 < 32);
        if (pre) {
            int k0n = (s + 1) * 16;
            uint32_t bd = (uint32_t)__cvta_generic_to_shared(&Bs[p ^ 1][bk][bc]);
            const int* bsrc = bptr + (long long)(k0n + bk) * H_DIM;
            CP16(bd, bsrc); CP16(bd + 16, bsrc + 4); CP16(bd + 32, bsrc + 8); CP16(bd + 48, bsrc + 12);
            CPCOMMIT();
            na0 = *(const int4*)(aptr + k0n);
            na1 = *(const int4*)(aptr + k0n + 4);
        }
        #pragma unroll
        for (int k4 = 0; k4 < 16; k4++) {
            int4 a0 = *(const int4*)&As[p][k4][m0];
            int4 a1 = *(const int4*)&As[p][k4][m0 + 4];
            int4 b0 = *(const int4*)&Bs[p][k4][n0];
            int4 b1 = *(const int4*)&Bs[p][k4][n0 + 4];
            int a[8] = {a0.x,a0.y,a0.z,a0.w,a1.x,a1.y,a1.z,a1.w};
            int b[8] = {b0.x,b0.y,b0.z,b0.w,b1.x,b1.y,b1.z,b1.w};
            #pragma unroll
            for (int i = 0; i < 8; i++)
                #pragma unroll
                for (int j = 0; j < 8; j++)
                    acc[i][j] = __dp4a(a[i], b[j], acc[i][j]);
        }
        if (pre) {
            int kb = ah * 8, pb = p ^ 1;
            As[pb][kb+0][am]=na0.x; As[pb][kb+1][am]=na0.y; As[pb][kb+2][am]=na0.z; As[pb][kb+3][am]=na0.w;
            As[pb][kb+4][am]=na1.x; As[pb][kb+5][am]=na1.y; As[pb][kb+6][am]=na1.z; As[pb][kb+7][am]=na1.w;
        }
        CPWAIT0();
        __syncthreads();
    }

    #pragma unroll
    for (int i = 0; i < 8; i++) {
        int m = m0 + i;
        float hs = s_hs[m];
        float* dst = g_z + ((size_t)e * CAP + mt * 64 + m) * H_DIM + (size_t)nt * 128 + n0;
        float4 r0, r1;
        #pragma unroll
        for (int j = 0; j < 8; j++) {
            int n = n0 + j;
            float z = (float)acc[i][j] * hs * s_zs[n] + s_zb[n];
            if (j < 4) ((float*)&r0)[j] = z; else ((float*)&r1)[j - 4] = z;
        }
        *(float4*)dst = r0;
        *(float4*)(dst + 4) = r1;
    }
}

// ---------------- combine ----------------
__global__ void k_combine(float* __restrict__ out) {
    int tkn = blockIdx.x, t = threadIdx.x;
    int h0 = t * 8;
    float r[8] = {0, 0, 0, 0, 0, 0, 0, 0};
    #pragma unroll
    for (int k = 0; k < K_TOP; k++) {
        int sl = g_slot[tkn * K_TOP + k];
        if (sl >= 0) {
            float w = g_topk_w[tkn * K_TOP + k];
            const float4* zp = (const float4*)&g_z[(size_t)sl * H_DIM + h0];
            float4 z0 = zp[0], z1 = zp[1];
            r[0] += w * z0.x; r[1] += w * z0.y; r[2] += w * z0.z; r[3] += w * z0.w;
            r[4] += w * z1.x; r[5] += w * z1.y; r[6] += w * z1.z; r[7] += w * z1.w;
        }
    }
    float* op = out + (size_t)tkn * H_DIM + h0;
    *(float4*)op       = make_float4(r[0], r[1], r[2], r[3]);
    *(float4*)(op + 4) = make_float4(r[4], r[5], r[6], r[7]);
}

// ---------------- launch ----------------
extern "C" void kernel_launch(void* const* d_in, const int* in_sizes, int n_in,
                              void* d_out, int out_size) {
    const float* hidden = (const float*)d_in[0];
    const float* logits = (const float*)d_in[1];
    const float* w1     = (const float*)d_in[2];
    const float* w1s    = (const float*)d_in[3];
    const float* w1b    = (const float*)d_in[4];
    const float* smooth = (const float*)d_in[5];
    const float* w2     = (const float*)d_in[6];
    const float* w2s    = (const float*)d_in[7];
    const float* w2b    = (const float*)d_in[8];
    float* out = (float*)d_out;

    // launch order chosen so the ncu capture (4th launch) lands on k_gemm1
    k_pack_all<<<49152, 256>>>(w1, w2);          // #1
    k_quant<<<T_TOK, 256>>>(hidden, 0);          // #2
    k_gateroute<<<1, 1024>>>(logits);            // #3
    k_gemm1<<<dim3(32, 8, E_EXP), 128>>>(w1s, w1b, smooth);   // #4  <- ncu
    k_quant<<<E_EXP * CAP, 256>>>(nullptr, 1);   // #5
    k_gemm2<<<dim3(16, 8, E_EXP), 128>>>(w2s, w2b);           // #6
    k_combine<<<T_TOK, 256>>>(out);              // #7
}